// round 1
// baseline (speedup 1.0000x reference)
#include <cuda_runtime.h>
#include <math.h>

#define NB 32768
#define NN 1024
#define NM 64
#define KTOT 128
#define TM 32
#define NC 128
#define NCHUNK 8
#define NSTAGE 16
#define PAIRS 64           // col-pairs per chunk
#define KS 64              // k per stage (half-chunk)
#define THREADS 256

// ---- device-global scratch (no allocations allowed) ----
__device__ __align__(16) float  g_logprior[NN];
__device__ __align__(16) float  g_inv_sd[NM];
__device__ __align__(16) float2 g_W[NSTAGE * KS * PAIRS];   // 512 KB, [stage][k'][pair]

typedef unsigned long long ull;

__device__ __forceinline__ void fma2(ull& d, ull a, ull b) {
    asm("fma.rn.f32x2 %0, %1, %2, %0;" : "+l"(d) : "l"(a), "l"(b));
}
__device__ __forceinline__ float2 asf2(ull v) {
    float2 r; asm("mov.b64 {%0,%1}, %2;" : "=f"(r.x), "=f"(r.y) : "l"(v)); return r;
}
__device__ __forceinline__ unsigned su32(const void* p) {
    return (unsigned)__cvta_generic_to_shared(p);
}
__device__ __forceinline__ void cp16(unsigned s, const void* g) {
    asm volatile("cp.async.cg.shared.global [%0], [%1], 16;" :: "r"(s), "l"(g) : "memory");
}

// ---- prep 1: inv_sd + log_softmax(log_marginal) ----
__global__ void prep_kernel(const float* __restrict__ sd, const float* __restrict__ lm) {
    __shared__ float red[THREADS];
    int t = threadIdx.x;
    if (t < NM) g_inv_sd[t] = 1.0f / sd[t];
    float mx = -1e30f;
    for (int i = t; i < NN; i += THREADS) mx = fmaxf(mx, lm[i]);
    red[t] = mx; __syncthreads();
    for (int s = THREADS / 2; s > 0; s >>= 1) {
        if (t < s) red[t] = fmaxf(red[t], red[t + s]);
        __syncthreads();
    }
    mx = red[0]; __syncthreads();
    float sum = 0.f;
    for (int i = t; i < NN; i += THREADS) sum += expf(lm[i] - mx);
    red[t] = sum; __syncthreads();
    for (int s = THREADS / 2; s > 0; s >>= 1) {
        if (t < s) red[t] += red[t + s];
        __syncthreads();
    }
    float lse = mx + logf(red[0]);
    for (int i = t; i < NN; i += THREADS) g_logprior[i] = lm[i] - lse;
}

// ---- prep 2: build W = [C ; -0.5*C^2] in stage/pair-interleaved layout ----
__global__ void prepw_kernel(const float* __restrict__ C) {
    int idx = blockIdx.x * blockDim.x + threadIdx.x;
    if (idx >= NSTAGE * KS * PAIRS) return;
    int pair  = idx & 63;
    int kp    = (idx >> 6) & 63;
    int stage = idx >> 12;
    int chunk = stage >> 1;
    int kg    = ((stage & 1) << 6) + kp;      // global folded-k index 0..127
    int n0    = chunk * NC + pair * 2;
    float2 v;
    if (kg < NM) {
        v.x = C[(size_t)n0 * NM + kg];
        v.y = C[(size_t)(n0 + 1) * NM + kg];
    } else {
        float c0 = C[(size_t)n0 * NM + kg - NM];
        float c1 = C[(size_t)(n0 + 1) * NM + kg - NM];
        v.x = -0.5f * c0 * c0;
        v.y = -0.5f * c1 * c1;
    }
    g_W[idx] = v;
}

// ---- main fused kernel ----
#define SMEM_LOGITS 0
#define SMEM_UD     (TM * NN * 4)                 // 131072
#define SMEM_W      (SMEM_UD + TM * KTOT * 8)     // 163840
#define SMEM_CB     (SMEM_W + 2 * KS * PAIRS * 8) // 229376
#define SMEM_TOTAL  (SMEM_CB + TM * 4)            // 229504

__global__ __launch_bounds__(THREADS, 1)
void rmm_main(const float* __restrict__ samples, const float* __restrict__ mask,
              float* __restrict__ out) {
    extern __shared__ char smem[];
    float*  sLog = (float*)(smem + SMEM_LOGITS);
    float2* sUd  = (float2*)(smem + SMEM_UD);
    float2* sW   = (float2*)(smem + SMEM_W);
    float*  sCb  = (float*)(smem + SMEM_CB);

    const int t    = threadIdx.x;
    const int warp = t >> 5;
    const int lane = t & 31;
    const int r0   = blockIdx.x * TM;

    // prologue: kick off stage-0 W panel copy
    {
        const float4* src = (const float4*)(g_W);
        float4* dstb = (float4*)sW;
        #pragma unroll
        for (int i = 0; i < 8; i++)
            cp16(su32(dstb + t + i * THREADS), src + t + i * THREADS);
        asm volatile("cp.async.commit_group;" ::: "memory");
    }

    // phase 0: build duplicated U rows and cb
    {
        int prow = t >> 3;
        int j0   = (t & 7) * 8;
        const float4* s4 = (const float4*)(samples + (size_t)(r0 + prow) * NM + j0);
        const float4* m4 = (const float4*)(mask    + (size_t)(r0 + prow) * NM + j0);
        float cbp = 0.f;
        #pragma unroll
        for (int q = 0; q < 2; q++) {
            float4 sv = s4[q];
            float4 mv = m4[q];
            int j = j0 + q * 4;
            float4 iv = *(const float4*)(g_inv_sd + j);
            float mm, sq, u;
            mm = mv.x * iv.x; sq = mm * mm; u = sq * sv.x; cbp += u * sv.x;
            sUd[prow * KTOT + j + 0] = make_float2(u, u);
            sUd[prow * KTOT + NM + j + 0] = make_float2(sq, sq);
            mm = mv.y * iv.y; sq = mm * mm; u = sq * sv.y; cbp += u * sv.y;
            sUd[prow * KTOT + j + 1] = make_float2(u, u);
            sUd[prow * KTOT + NM + j + 1] = make_float2(sq, sq);
            mm = mv.z * iv.z; sq = mm * mm; u = sq * sv.z; cbp += u * sv.z;
            sUd[prow * KTOT + j + 2] = make_float2(u, u);
            sUd[prow * KTOT + NM + j + 2] = make_float2(sq, sq);
            mm = mv.w * iv.w; sq = mm * mm; u = sq * sv.w; cbp += u * sv.w;
            sUd[prow * KTOT + j + 3] = make_float2(u, u);
            sUd[prow * KTOT + NM + j + 3] = make_float2(sq, sq);
        }
        cbp += __shfl_xor_sync(0xffffffffu, cbp, 1);
        cbp += __shfl_xor_sync(0xffffffffu, cbp, 2);
        cbp += __shfl_xor_sync(0xffffffffu, cbp, 4);
        if ((t & 7) == 0) sCb[prow] = -0.5f * cbp;
    }
    __syncthreads();

    const int rg = warp >> 1;
    const int p  = ((warp & 1) << 5) | lane;   // col-pair 0..63 within chunk

    float cbr[8];
    #pragma unroll
    for (int i = 0; i < 8; i++) cbr[i] = sCb[rg * 8 + i];

    ull acc[8];
    #pragma unroll
    for (int i = 0; i < 8; i++) acc[i] = 0ull;

    for (int s = 0; s < NSTAGE; s++) {
        asm volatile("cp.async.wait_group 0;" ::: "memory");
        __syncthreads();
        if (s + 1 < NSTAGE) {
            const float4* src = (const float4*)(g_W + (size_t)(s + 1) * (KS * PAIRS));
            float4* dstb = (float4*)(sW + ((s + 1) & 1) * (KS * PAIRS));
            #pragma unroll
            for (int i = 0; i < 8; i++)
                cp16(su32(dstb + t + i * THREADS), src + t + i * THREADS);
            asm volatile("cp.async.commit_group;" ::: "memory");
        }
        const ull* wp = (const ull*)(sW + (s & 1) * (KS * PAIRS));
        const int kb = (s & 1) * 32;  // ulonglong2 offset into each Ud row

        const ulonglong2* u0 = (const ulonglong2*)(sUd + (rg * 8 + 0) * KTOT) + kb;
        const ulonglong2* u1 = (const ulonglong2*)(sUd + (rg * 8 + 1) * KTOT) + kb;
        const ulonglong2* u2 = (const ulonglong2*)(sUd + (rg * 8 + 2) * KTOT) + kb;
        const ulonglong2* u3 = (const ulonglong2*)(sUd + (rg * 8 + 3) * KTOT) + kb;
        const ulonglong2* u4 = (const ulonglong2*)(sUd + (rg * 8 + 4) * KTOT) + kb;
        const ulonglong2* u5 = (const ulonglong2*)(sUd + (rg * 8 + 5) * KTOT) + kb;
        const ulonglong2* u6 = (const ulonglong2*)(sUd + (rg * 8 + 6) * KTOT) + kb;
        const ulonglong2* u7 = (const ulonglong2*)(sUd + (rg * 8 + 7) * KTOT) + kb;

        #pragma unroll
        for (int kk = 0; kk < 32; kk++) {
            ull b0 = wp[(2 * kk) * PAIRS + p];
            ull b1 = wp[(2 * kk + 1) * PAIRS + p];
            ulonglong2 a;
            a = u0[kk]; fma2(acc[0], a.x, b0); fma2(acc[0], a.y, b1);
            a = u1[kk]; fma2(acc[1], a.x, b0); fma2(acc[1], a.y, b1);
            a = u2[kk]; fma2(acc[2], a.x, b0); fma2(acc[2], a.y, b1);
            a = u3[kk]; fma2(acc[3], a.x, b0); fma2(acc[3], a.y, b1);
            a = u4[kk]; fma2(acc[4], a.x, b0); fma2(acc[4], a.y, b1);
            a = u5[kk]; fma2(acc[5], a.x, b0); fma2(acc[5], a.y, b1);
            a = u6[kk]; fma2(acc[6], a.x, b0); fma2(acc[6], a.y, b1);
            a = u7[kk]; fma2(acc[7], a.x, b0); fma2(acc[7], a.y, b1);
        }

        if (s & 1) {  // chunk complete: epilogue -> logits smem, reset acc
            int chunk = s >> 1;
            int col = chunk * NC + p * 2;
            float2 lp = *(const float2*)(g_logprior + col);
            #pragma unroll
            for (int i = 0; i < 8; i++) {
                float2 av = asf2(acc[i]);
                float v0 = lp.x + fminf(av.x + cbr[i], 0.f);
                float v1 = lp.y + fminf(av.y + cbr[i], 0.f);
                *(float2*)(sLog + (size_t)(rg * 8 + i) * NN + col) = make_float2(v0, v1);
                acc[i] = 0ull;
            }
        }
    }
    __syncthreads();

    // phase 2: per-row truncated softmax (normalizer of first softmax cancels)
    float* pdf_out  = out;
    float* lpdf_out = out + (size_t)NB * NN;
    #pragma unroll 1
    for (int rr = 0; rr < 4; rr++) {
        int row = rr * 8 + warp;
        const float4* L4 = (const float4*)(sLog + (size_t)row * NN);
        float4 x[8];
        #pragma unroll
        for (int i = 0; i < 8; i++) x[i] = L4[lane + 32 * i];
        float mx = -1e30f;
        #pragma unroll
        for (int i = 0; i < 8; i++)
            mx = fmaxf(mx, fmaxf(fmaxf(x[i].x, x[i].y), fmaxf(x[i].z, x[i].w)));
        #pragma unroll
        for (int o = 16; o > 0; o >>= 1)
            mx = fmaxf(mx, __shfl_xor_sync(0xffffffffu, mx, o));
        float ssum = 0.f;
        #pragma unroll
        for (int i = 0; i < 8; i++) {
            float4 v = x[i];
            float p0 = __expf(v.x - mx); p0 = (p0 > 0.05f) ? p0 : 0.f;
            float p1 = __expf(v.y - mx); p1 = (p1 > 0.05f) ? p1 : 0.f;
            float p2 = __expf(v.z - mx); p2 = (p2 > 0.05f) ? p2 : 0.f;
            float p3 = __expf(v.w - mx); p3 = (p3 > 0.05f) ? p3 : 0.f;
            x[i] = make_float4(p0, p1, p2, p3);
            ssum += (p0 + p1) + (p2 + p3);
        }
        #pragma unroll
        for (int o = 16; o > 0; o >>= 1)
            ssum += __shfl_xor_sync(0xffffffffu, ssum, o);
        float inv = 1.0f / ssum;
        size_t rb = (size_t)(r0 + row) * NN;
        float4* po = (float4*)(pdf_out + rb);
        float4* lo = (float4*)(lpdf_out + rb);
        #pragma unroll
        for (int i = 0; i < 8; i++) {
            float4 v = x[i];
            float4 P = make_float4(v.x * inv, v.y * inv, v.z * inv, v.w * inv);
            float4 L = make_float4(__logf(P.x + 1e-20f), __logf(P.y + 1e-20f),
                                   __logf(P.z + 1e-20f), __logf(P.w + 1e-20f));
            po[lane + 32 * i] = P;
            lo[lane + 32 * i] = L;
        }
    }
}

extern "C" void kernel_launch(void* const* d_in, const int* in_sizes, int n_in,
                              void* d_out, int out_size) {
    const float* samples = (const float*)d_in[0];
    const float* mask    = (const float*)d_in[1];
    const float* cent    = (const float*)d_in[2];
    const float* sd      = (const float*)d_in[3];
    const float* lm      = (const float*)d_in[4];
    float* out = (float*)d_out;
    (void)in_sizes; (void)n_in; (void)out_size;

    cudaFuncSetAttribute(rmm_main, cudaFuncAttributeMaxDynamicSharedMemorySize, SMEM_TOTAL);

    prep_kernel<<<1, THREADS>>>(sd, lm);
    prepw_kernel<<<(NSTAGE * KS * PAIRS + THREADS - 1) / THREADS, THREADS>>>(cent);
    rmm_main<<<NB / TM, THREADS, SMEM_TOTAL>>>(samples, mask, out);
}

// round 2
// speedup vs baseline: 1.4163x; 1.4163x over previous
#include <cuda_runtime.h>
#include <math.h>

#define NB 32768
#define NN 1024
#define NM 64
#define KTOT 128
#define TM 32
#define THREADS 256
#define NSTAGE 16
#define WSTAGE_F2 4096    // 16 ks * 4 chunks * 64 pairs per stage

// ---- device-global scratch (no allocations allowed) ----
__device__ __align__(16) float  g_logprior[NN];
__device__ __align__(16) float  g_inv_sd[NM];
__device__ __align__(16) float2 g_W[NSTAGE * WSTAGE_F2];   // 512 KB

typedef unsigned long long ull;

__device__ __forceinline__ void fma2(ull& d, ull a, ull b) {
    asm("fma.rn.f32x2 %0, %1, %2, %0;" : "+l"(d) : "l"(a), "l"(b));
}
__device__ __forceinline__ float2 asf2(ull v) {
    float2 r; asm("mov.b64 {%0,%1}, %2;" : "=f"(r.x), "=f"(r.y) : "l"(v)); return r;
}
__device__ __forceinline__ unsigned su32(const void* p) {
    return (unsigned)__cvta_generic_to_shared(p);
}
__device__ __forceinline__ void cp16(unsigned s, const void* g) {
    asm volatile("cp.async.cg.shared.global [%0], [%1], 16;" :: "r"(s), "l"(g) : "memory");
}

// ---- single prep kernel: block 0 builds inv_sd + log_softmax(lm); all blocks build W ----
__global__ void prep_all(const float* __restrict__ C, const float* __restrict__ sd,
                         const float* __restrict__ lm) {
    __shared__ float red[THREADS];
    int t = threadIdx.x;
    if (blockIdx.x == 0) {
        if (t < NM) g_inv_sd[t] = 1.0f / sd[t];
        float mx = -1e30f;
        for (int i = t; i < NN; i += THREADS) mx = fmaxf(mx, lm[i]);
        red[t] = mx; __syncthreads();
        for (int s = THREADS / 2; s > 0; s >>= 1) {
            if (t < s) red[t] = fmaxf(red[t], red[t + s]);
            __syncthreads();
        }
        mx = red[0]; __syncthreads();
        float sum = 0.f;
        for (int i = t; i < NN; i += THREADS) sum += expf(lm[i] - mx);
        red[t] = sum; __syncthreads();
        for (int s = THREADS / 2; s > 0; s >>= 1) {
            if (t < s) red[t] += red[t + s];
            __syncthreads();
        }
        float lse = mx + logf(red[0]);
        for (int i = t; i < NN; i += THREADS) g_logprior[i] = lm[i] - lse;
    }
    // W layout: [stage16][kp16][chunk4][pair64] as float2 over cols (pair*2, pair*2+1)
    int idx = blockIdx.x * blockDim.x + t;
    if (idx >= NSTAGE * WSTAGE_F2) return;
    int pair = idx & 63;
    int ch   = (idx >> 6) & 3;
    int kp   = (idx >> 8) & 15;
    int sg   = idx >> 12;          // global stage 0..15
    int pass = sg >> 3;            // col pass 0/1
    int st   = sg & 7;             // k-stage within pass
    int k    = st * 16 + kp;       // folded k 0..127
    int gc   = pass * 4 + ch;      // global chunk 0..7
    int n0   = gc * 128 + pair * 2;
    float2 v;
    if (k < NM) {
        v.x = C[(size_t)n0 * NM + k];
        v.y = C[(size_t)(n0 + 1) * NM + k];
    } else {
        float c0 = C[(size_t)n0 * NM + k - NM];
        float c1 = C[(size_t)(n0 + 1) * NM + k - NM];
        v.x = -0.5f * c0 * c0;
        v.y = -0.5f * c1 * c1;
    }
    g_W[idx] = v;
}

// ---- main fused kernel ----
#define SMEM_LOGITS 0
#define SMEM_UD     (TM * NN * 4)                  // 131072
#define SMEM_W      (SMEM_UD + TM * KTOT * 8)      // 163840
#define SMEM_CB     (SMEM_W + 2 * WSTAGE_F2 * 8)   // 229376
#define SMEM_TOTAL  (SMEM_CB + TM * 4)             // 229504

__global__ __launch_bounds__(THREADS, 1)
void rmm_main(const float* __restrict__ samples, const float* __restrict__ mask,
              float* __restrict__ out) {
    extern __shared__ char smem[];
    float*  sLog = (float*)(smem + SMEM_LOGITS);
    float2* sUd  = (float2*)(smem + SMEM_UD);
    float2* sW   = (float2*)(smem + SMEM_W);
    float*  sCb  = (float*)(smem + SMEM_CB);

    const int t    = threadIdx.x;
    const int warp = t >> 5;
    const int lane = t & 31;
    const int r0   = blockIdx.x * TM;

    // prologue: kick off stage-0 W panel copy (32 KB)
    {
        const float4* src = (const float4*)(g_W);
        float4* dstb = (float4*)sW;
        #pragma unroll
        for (int i = 0; i < 8; i++)
            cp16(su32(dstb + t + i * THREADS), src + t + i * THREADS);
        asm volatile("cp.async.commit_group;" ::: "memory");
    }

    // phase 0: build duplicated U rows and cb
    {
        int prow = t >> 3;
        int j0   = (t & 7) * 8;
        const float4* s4 = (const float4*)(samples + (size_t)(r0 + prow) * NM + j0);
        const float4* m4 = (const float4*)(mask    + (size_t)(r0 + prow) * NM + j0);
        float cbp = 0.f;
        #pragma unroll
        for (int q = 0; q < 2; q++) {
            float4 sv = s4[q];
            float4 mv = m4[q];
            int j = j0 + q * 4;
            float4 iv = *(const float4*)(g_inv_sd + j);
            float mm, sq, u;
            mm = mv.x * iv.x; sq = mm * mm; u = sq * sv.x; cbp += u * sv.x;
            sUd[prow * KTOT + j + 0] = make_float2(u, u);
            sUd[prow * KTOT + NM + j + 0] = make_float2(sq, sq);
            mm = mv.y * iv.y; sq = mm * mm; u = sq * sv.y; cbp += u * sv.y;
            sUd[prow * KTOT + j + 1] = make_float2(u, u);
            sUd[prow * KTOT + NM + j + 1] = make_float2(sq, sq);
            mm = mv.z * iv.z; sq = mm * mm; u = sq * sv.z; cbp += u * sv.z;
            sUd[prow * KTOT + j + 2] = make_float2(u, u);
            sUd[prow * KTOT + NM + j + 2] = make_float2(sq, sq);
            mm = mv.w * iv.w; sq = mm * mm; u = sq * sv.w; cbp += u * sv.w;
            sUd[prow * KTOT + j + 3] = make_float2(u, u);
            sUd[prow * KTOT + NM + j + 3] = make_float2(sq, sq);
        }
        cbp += __shfl_xor_sync(0xffffffffu, cbp, 1);
        cbp += __shfl_xor_sync(0xffffffffu, cbp, 2);
        cbp += __shfl_xor_sync(0xffffffffu, cbp, 4);
        if ((t & 7) == 0) sCb[prow] = -0.5f * cbp;
    }

    // mapping: warp -> (chunk = warp>>1, row half = warp&1); lane -> pairs lane & lane+32
    const int mych  = warp >> 1;           // chunk within the 4-chunk pass
    const int rbase = (warp & 1) * 16;     // 16 rows per warp
    const ulonglong2* uBase = (const ulonglong2*)(sUd) + rbase * 64;  // 64 ull2 per row

    ull acc0[16], acc1[16];
    #pragma unroll
    for (int i = 0; i < 16; i++) { acc0[i] = 0ull; acc1[i] = 0ull; }

    __syncthreads();

    #pragma unroll 1
    for (int s = 0; s < NSTAGE; s++) {
        asm volatile("cp.async.wait_group 0;" ::: "memory");
        __syncthreads();
        if (s + 1 < NSTAGE) {
            const float4* src = (const float4*)(g_W + (size_t)(s + 1) * WSTAGE_F2);
            float4* dstb = (float4*)(sW + ((s + 1) & 1) * WSTAGE_F2);
            #pragma unroll
            for (int i = 0; i < 8; i++)
                cp16(su32(dstb + t + i * THREADS), src + t + i * THREADS);
            asm volatile("cp.async.commit_group;" ::: "memory");
        }

        const ull* wbL = (const ull*)(sW + (s & 1) * WSTAGE_F2) + mych * 64 + lane;
        const ulonglong2* uS = uBase + (s & 7) * 8;

        #pragma unroll
        for (int kk = 0; kk < 8; kk++) {
            ull b00 = wbL[(2 * kk) * 256];
            ull b01 = wbL[(2 * kk + 1) * 256];
            ull b10 = wbL[(2 * kk) * 256 + 32];
            ull b11 = wbL[(2 * kk + 1) * 256 + 32];
            #pragma unroll
            for (int r = 0; r < 16; r++) {
                ulonglong2 a = uS[r * 64 + kk];
                fma2(acc0[r], a.x, b00); fma2(acc0[r], a.y, b01);
                fma2(acc1[r], a.x, b10); fma2(acc1[r], a.y, b11);
            }
        }

        if ((s & 7) == 7) {   // pass complete for this warp's chunk -> logits
            int gc = (s >> 3) * 4 + mych;
            int c0 = gc * 128 + lane * 2;
            float2 lp0 = *(const float2*)(g_logprior + c0);
            float2 lp1 = *(const float2*)(g_logprior + c0 + 64);
            #pragma unroll
            for (int r = 0; r < 16; r++) {
                float cb = sCb[rbase + r];
                float2 a0 = asf2(acc0[r]);
                float2 a1 = asf2(acc1[r]);
                float2 v0 = make_float2(lp0.x + fminf(a0.x + cb, 0.f),
                                        lp0.y + fminf(a0.y + cb, 0.f));
                float2 v1 = make_float2(lp1.x + fminf(a1.x + cb, 0.f),
                                        lp1.y + fminf(a1.y + cb, 0.f));
                float* row = sLog + (size_t)(rbase + r) * NN + c0;
                *(float2*)(row)      = v0;
                *(float2*)(row + 64) = v1;
                acc0[r] = 0ull; acc1[r] = 0ull;
            }
        }
    }
    __syncthreads();

    // phase 2: per-row truncated softmax (first softmax's normalizer cancels)
    float* pdf_out  = out;
    float* lpdf_out = out + (size_t)NB * NN;
    #pragma unroll 1
    for (int rr = 0; rr < 4; rr++) {
        int row = rr * 8 + warp;
        const float4* L4 = (const float4*)(sLog + (size_t)row * NN);
        float4 x[8];
        #pragma unroll
        for (int i = 0; i < 8; i++) x[i] = L4[lane + 32 * i];
        float mx = -1e30f;
        #pragma unroll
        for (int i = 0; i < 8; i++)
            mx = fmaxf(mx, fmaxf(fmaxf(x[i].x, x[i].y), fmaxf(x[i].z, x[i].w)));
        #pragma unroll
        for (int o = 16; o > 0; o >>= 1)
            mx = fmaxf(mx, __shfl_xor_sync(0xffffffffu, mx, o));
        float ssum = 0.f;
        #pragma unroll
        for (int i = 0; i < 8; i++) {
            float4 v = x[i];
            float p0 = __expf(v.x - mx); p0 = (p0 > 0.05f) ? p0 : 0.f;
            float p1 = __expf(v.y - mx); p1 = (p1 > 0.05f) ? p1 : 0.f;
            float p2 = __expf(v.z - mx); p2 = (p2 > 0.05f) ? p2 : 0.f;
            float p3 = __expf(v.w - mx); p3 = (p3 > 0.05f) ? p3 : 0.f;
            x[i] = make_float4(p0, p1, p2, p3);
            ssum += (p0 + p1) + (p2 + p3);
        }
        #pragma unroll
        for (int o = 16; o > 0; o >>= 1)
            ssum += __shfl_xor_sync(0xffffffffu, ssum, o);
        float inv = 1.0f / ssum;
        size_t rb = (size_t)(r0 + row) * NN;
        float4* po = (float4*)(pdf_out + rb);
        float4* lo = (float4*)(lpdf_out + rb);
        #pragma unroll
        for (int i = 0; i < 8; i++) {
            float4 v = x[i];
            float4 P = make_float4(v.x * inv, v.y * inv, v.z * inv, v.w * inv);
            float4 L = make_float4(__logf(P.x + 1e-20f), __logf(P.y + 1e-20f),
                                   __logf(P.z + 1e-20f), __logf(P.w + 1e-20f));
            po[lane + 32 * i] = P;
            lo[lane + 32 * i] = L;
        }
    }
}

extern "C" void kernel_launch(void* const* d_in, const int* in_sizes, int n_in,
                              void* d_out, int out_size) {
    const float* samples = (const float*)d_in[0];
    const float* mask    = (const float*)d_in[1];
    const float* cent    = (const float*)d_in[2];
    const float* sd      = (const float*)d_in[3];
    const float* lm      = (const float*)d_in[4];
    float* out = (float*)d_out;
    (void)in_sizes; (void)n_in; (void)out_size;

    cudaFuncSetAttribute(rmm_main, cudaFuncAttributeMaxDynamicSharedMemorySize, SMEM_TOTAL);

    prep_all<<<(NSTAGE * WSTAGE_F2 + THREADS - 1) / THREADS, THREADS>>>(cent, sd, lm);
    rmm_main<<<NB / TM, THREADS, SMEM_TOTAL>>>(samples, mask, out);
}